// round 8
// baseline (speedup 1.0000x reference)
#include <cuda_runtime.h>
#include <math.h>

// ---------------------------------------------------------------------------
// JPEG round-trip:  (32, 3, 512, 512) fp32, quality scalar.
// One CTA (256 threads) = one 8-row x 512-col strip of one image.
//   Phase A: load RGB, color fwd (Cb/Cr packed f32x2), ROW-DCT (Y scalar,
//            UV packed) -> pair-interleaved smem (all STS.64, conflict-free)
//   Phase B: column pass: Y as packed col-pairs, UV as naturally-packed
//            (u,v) columns; quant via fused tables; all LDS/STS.64 clean.
//   Phase C: ROW-IDCT (Y scalar, UV packed), color inv, store.
// __launch_bounds__(256,4): 64-reg cap -> 32 warps/SM.
// ---------------------------------------------------------------------------

#define NB 32
#define NH 512
#define NW 512
// Y plane:  4096 floats, pair-interleaved: r*512 + q*128 + bx*2   (q=colpair)
// UV plane: 8192 floats, (u,v) interleaved: r*1024 + j*128 + bx*2 (j=col)
#define YOFF   0
#define UVOFF  4096
#define QL4    12288                     // float4 qlum4[32] = 128 floats
#define QC2    12416                     // float2 qchr2[64] = 128 floats
#define SMEM_BYTES (12544 * 4)

static __device__ const float LUMT[64] = {
    16,11,10,16,24,40,51,61,
    12,12,14,19,26,58,60,55,
    14,13,16,24,40,57,69,56,
    14,17,22,29,51,87,80,62,
    18,22,37,56,68,109,103,77,
    24,35,55,64,81,104,113,92,
    49,64,78,87,103,121,120,101,
    72,92,95,98,112,100,103,99};
static __device__ const float CHRT[64] = {
    17,18,24,47,99,99,99,99,
    18,21,26,66,99,99,99,99,
    24,26,56,99,99,99,99,99,
    47,66,99,99,99,99,99,99,
    99,99,99,99,99,99,99,99,
    99,99,99,99,99,99,99,99,
    99,99,99,99,99,99,99,99,
    99,99,99,99,99,99,99,99};

// 0.5*cos(k*pi/16)
#define CA  0.35355339059327373f
#define CC1 0.49039264020161522f
#define CC2 0.46193976625564337f
#define CC3 0.41573480615127262f
#define CC5 0.27778511650980114f
#define CC6 0.19134171618254492f
#define CC7 0.097545161008064166f

// ---------------- f32x2 packed helpers (sm_103a) ---------------------------
typedef unsigned long long u64t;

__device__ __forceinline__ u64t pk2(float a, float b) {
    u64t r; asm("mov.b64 %0, {%1, %2};" : "=l"(r) : "f"(a), "f"(b)); return r;
}
__device__ __forceinline__ void upk2(u64t v, float& a, float& b) {
    asm("mov.b64 {%0, %1}, %2;" : "=f"(a), "=f"(b) : "l"(v));
}
__device__ __forceinline__ u64t dup2(float c) {
    u64t r; asm("mov.b64 %0, {%1, %1};" : "=l"(r) : "f"(c)); return r;
}
__device__ __forceinline__ u64t add2(u64t a, u64t b) {
    u64t d; asm("add.rn.f32x2 %0, %1, %2;" : "=l"(d) : "l"(a), "l"(b)); return d;
}
__device__ __forceinline__ u64t mul2(u64t a, u64t b) {
    u64t d; asm("mul.rn.f32x2 %0, %1, %2;" : "=l"(d) : "l"(a), "l"(b)); return d;
}
__device__ __forceinline__ u64t fma2(u64t a, u64t b, u64t c) {
    u64t d; asm("fma.rn.f32x2 %0, %1, %2, %3;" : "=l"(d) : "l"(a), "l"(b), "l"(c));
    return d;
}
// exact a - b  (fma(b,-1,a): -1*b exact, single rounding == sub.rn)
__device__ __forceinline__ u64t sub2(u64t a, u64t b) {
    return fma2(b, dup2(-1.0f), a);
}

__device__ __forceinline__ void dct8p(u64t* v) {
    const u64t kA = dup2(CA), k1 = dup2(CC1), k2 = dup2(CC2), k3 = dup2(CC3);
    const u64t k5 = dup2(CC5), k6 = dup2(CC6), k7 = dup2(CC7);
    const u64t n1 = dup2(-CC1), n2 = dup2(-CC2), n5 = dup2(-CC5), n7 = dup2(-CC7);
    u64t s0 = add2(v[0], v[7]), s1 = add2(v[1], v[6]);
    u64t s2 = add2(v[2], v[5]), s3 = add2(v[3], v[4]);
    u64t d0 = sub2(v[0], v[7]), d1 = sub2(v[1], v[6]);
    u64t d2 = sub2(v[2], v[5]), d3 = sub2(v[3], v[4]);
    u64t e0 = add2(s0, s3), e1 = add2(s1, s2);
    u64t f0 = sub2(s0, s3), f1 = sub2(s1, s2);
    v[0] = mul2(kA, add2(e0, e1));
    v[4] = mul2(kA, sub2(e0, e1));
    v[2] = fma2(k2, f0, mul2(k6, f1));
    v[6] = fma2(k6, f0, mul2(n2, f1));
    v[1] = fma2(k1, d0, fma2(k3, d1, fma2(k5, d2, mul2(k7, d3))));
    v[3] = fma2(k3, d0, fma2(n7, d1, fma2(n1, d2, mul2(n5, d3))));
    v[5] = fma2(k5, d0, fma2(n1, d1, fma2(k7, d2, mul2(k3, d3))));
    v[7] = fma2(k7, d0, fma2(n5, d1, fma2(k3, d2, mul2(n1, d3))));
}

__device__ __forceinline__ void idct8p(u64t* v) {
    const u64t kA = dup2(CA), k1 = dup2(CC1), k2 = dup2(CC2), k3 = dup2(CC3);
    const u64t k5 = dup2(CC5), k6 = dup2(CC6), k7 = dup2(CC7);
    const u64t n1 = dup2(-CC1), n2 = dup2(-CC2), n5 = dup2(-CC5), n7 = dup2(-CC7);
    u64t x0 = v[0], x1 = v[1], x2 = v[2], x3 = v[3];
    u64t x4 = v[4], x5 = v[5], x6 = v[6], x7 = v[7];
    u64t ea = mul2(kA, add2(x0, x4));
    u64t eb = mul2(kA, sub2(x0, x4));
    u64t ec = fma2(k2, x2, mul2(k6, x6));
    u64t ed = fma2(k6, x2, mul2(n2, x6));
    u64t e0 = add2(ea, ec), e1 = add2(eb, ed);
    u64t e2 = sub2(eb, ed), e3 = sub2(ea, ec);
    u64t o0 = fma2(k1, x1, fma2(k3, x3, fma2(k5, x5, mul2(k7, x7))));
    u64t o1 = fma2(k3, x1, fma2(n7, x3, fma2(n1, x5, mul2(n5, x7))));
    u64t o2 = fma2(k5, x1, fma2(n1, x3, fma2(k7, x5, mul2(k3, x7))));
    u64t o3 = fma2(k7, x1, fma2(n5, x3, fma2(k3, x5, mul2(n1, x7))));
    v[0] = add2(e0, o0);  v[7] = sub2(e0, o0);
    v[1] = add2(e1, o1);  v[6] = sub2(e1, o1);
    v[2] = add2(e2, o2);  v[5] = sub2(e2, o2);
    v[3] = add2(e3, o3);  v[4] = sub2(e3, o3);
}

// ---------------- scalar DCT (Y path, unchanged numerics) ------------------
__device__ __forceinline__ void dct8(float* v) {
    float x0 = v[0], x1 = v[1], x2 = v[2], x3 = v[3];
    float x4 = v[4], x5 = v[5], x6 = v[6], x7 = v[7];
    float s0 = x0 + x7, s1 = x1 + x6, s2 = x2 + x5, s3 = x3 + x4;
    float d0 = x0 - x7, d1 = x1 - x6, d2 = x2 - x5, d3 = x3 - x4;
    float e0 = s0 + s3, e1 = s1 + s2;
    float f0 = s0 - s3, f1 = s1 - s2;
    v[0] = CA * (e0 + e1);
    v[4] = CA * (e0 - e1);
    v[2] = fmaf(CC2, f0,  CC6 * f1);
    v[6] = fmaf(CC6, f0, -(CC2 * f1));
    v[1] = fmaf(CC1, d0, fmaf( CC3, d1, fmaf( CC5, d2,  CC7 * d3)));
    v[3] = fmaf(CC3, d0, fmaf(-CC7, d1, fmaf(-CC1, d2, -(CC5 * d3))));
    v[5] = fmaf(CC5, d0, fmaf(-CC1, d1, fmaf( CC7, d2,  CC3 * d3)));
    v[7] = fmaf(CC7, d0, fmaf(-CC5, d1, fmaf( CC3, d2, -(CC1 * d3))));
}

__device__ __forceinline__ void idct8(float* v) {
    float x0 = v[0], x1 = v[1], x2 = v[2], x3 = v[3];
    float x4 = v[4], x5 = v[5], x6 = v[6], x7 = v[7];
    float ea = CA * (x0 + x4);
    float eb = CA * (x0 - x4);
    float ec = fmaf(CC2, x2,  CC6 * x6);
    float ed = fmaf(CC6, x2, -(CC2 * x6));
    float e0 = ea + ec, e1 = eb + ed, e2 = eb - ed, e3 = ea - ec;
    float o0 = fmaf(CC1, x1, fmaf( CC3, x3, fmaf( CC5, x5,  CC7 * x7)));
    float o1 = fmaf(CC3, x1, fmaf(-CC7, x3, fmaf(-CC1, x5, -(CC5 * x7))));
    float o2 = fmaf(CC5, x1, fmaf(-CC1, x3, fmaf( CC7, x5,  CC3 * x7)));
    float o3 = fmaf(CC7, x1, fmaf(-CC5, x3, fmaf( CC3, x5, -(CC1 * x7))));
    v[0] = e0 + o0;  v[7] = e0 - o0;
    v[1] = e1 + o1;  v[6] = e1 - o1;
    v[2] = e2 + o2;  v[5] = e2 - o2;
    v[3] = e3 + o3;  v[4] = e3 - o3;
}

__device__ __forceinline__ float to255(float x) {
    return rintf(__fmul_rn(fminf(fmaxf(x, 0.0f), 1.0f), 255.0f));
}

__device__ __forceinline__ float qscale(int qi, float base) {
    double scale = (qi < 50) ? 5000.0 / (double)qi : 200.0 - 2.0 * (double)qi;
    double v = floor(((double)base * scale + 50.0) / 100.0);
    v = (v < 1.0) ? 1.0 : ((v > 255.0) ? 255.0 : v);
    return (float)v;
}

// color fwd for one pixel: Y scalar out, (Cb-128, Cr-128) packed out.
__device__ __forceinline__ void fwd_px_p(float r, float g, float bl,
                                         float& y, u64t& uv) {
    r = to255(r); g = to255(g); bl = to255(bl);
    float yv = __fadd_rn(__fadd_rn(__fmul_rn(0.299f, r), __fmul_rn(0.587f, g)),
                         __fmul_rn(0.114f, bl));
    y = __fsub_rn(yv, 128.0f);
    const u64t KR = pk2(-0.168736f, 0.5f);
    const u64t KG = pk2( 0.331264f, 0.418688f);
    const u64t KB = pk2( 0.5f,     -0.081312f);
    const u64t K128 = dup2(128.0f);
    u64t m1 = mul2(KR, dup2(r));
    u64t m2 = mul2(KG, dup2(g));
    u64t m3 = mul2(KB, dup2(bl));
    u64t s  = sub2(m1, m2);          // lane0: cb t1-t2 ; lane1: cr t1-t2
    s = add2(s, m3);                 // lane1 adds -0.081312*b == sub
    s = add2(s, K128);
    uv = sub2(s, K128);
}

__global__ void __launch_bounds__(256, 4)
jpeg_kernel(const float* __restrict__ in, const int* __restrict__ qp,
            float* __restrict__ out) {
    extern __shared__ float sm[];
    const int t  = threadIdx.x;
    const int by = blockIdx.x;   // block-row (H/8 = 64)
    const int b  = blockIdx.y;   // batch

    // ---- quant tables: qlum4[32]=(q0,q1,1/q0,1/q1), qchr2[64]=(q,1/q) ----
    {
        int qi = qp[0];
        if (qi < 1 || qi > 100) {           // scalar may arrive as float bits
            float f = __int_as_float(qi);
            qi = (int)f;
        }
        if (qi < 1) qi = 1;
        if (qi > 100) qi = 100;
        if (t < 32) {
            float q0 = qscale(qi, LUMT[2 * t]);
            float q1 = qscale(qi, LUMT[2 * t + 1]);
            ((float4*)(sm + QL4))[t] = make_float4(q0, q1, 1.0f / q0, 1.0f / q1);
        } else if (t < 96) {
            int idx = t - 32;
            float q0 = qscale(qi, CHRT[idx]);
            ((float2*)(sm + QC2))[idx] = make_float2(q0, 1.0f / q0);
        }
    }

    const size_t pstride = (size_t)NH * NW;
    const float* pr = in + ((size_t)b * 3 + 0) * pstride + (size_t)by * 8 * NW;
    const float* pg = pr + pstride;
    const float* pb = pg + pstride;

    // ---- Phase A: load + color fwd + ROW-DCT -> smem ---------------------
    #pragma unroll
    for (int it = 0; it < 2; it++) {
        int i  = t + it * 256;               // 512 items: (row, block)
        int r  = i >> 6, bx = i & 63;
        const float* rp = pr + r * NW + bx * 8;
        const float* gp = pg + r * NW + bx * 8;
        const float* bp = pb + r * NW + bx * 8;
        float Y[8]; u64t uv[8];
        {   // first half-row
            float4 R4 = *(const float4*)rp;
            float4 G4 = *(const float4*)gp;
            float4 B4 = *(const float4*)bp;
            fwd_px_p(R4.x, G4.x, B4.x, Y[0], uv[0]);
            fwd_px_p(R4.y, G4.y, B4.y, Y[1], uv[1]);
            fwd_px_p(R4.z, G4.z, B4.z, Y[2], uv[2]);
            fwd_px_p(R4.w, G4.w, B4.w, Y[3], uv[3]);
        }
        {   // second half-row
            float4 R4 = *(const float4*)(rp + 4);
            float4 G4 = *(const float4*)(gp + 4);
            float4 B4 = *(const float4*)(bp + 4);
            fwd_px_p(R4.x, G4.x, B4.x, Y[4], uv[4]);
            fwd_px_p(R4.y, G4.y, B4.y, Y[5], uv[5]);
            fwd_px_p(R4.z, G4.z, B4.z, Y[6], uv[6]);
            fwd_px_p(R4.w, G4.w, B4.w, Y[7], uv[7]);
        }
        dct8(Y);
        dct8p(uv);
        float* py = sm + YOFF + r * 512 + bx * 2;
        #pragma unroll
        for (int q = 0; q < 4; q++)
            *(float2*)(py + q * 128) = make_float2(Y[2 * q], Y[2 * q + 1]);
        float* pu = sm + UVOFF + r * 1024 + bx * 2;
        #pragma unroll
        for (int j = 0; j < 8; j++) {
            float a, bb2; upk2(uv[j], a, bb2);
            *(float2*)(pu + j * 128) = make_float2(a, bb2);
        }
    }
    __syncthreads();

    // ---- Phase B: column pass (Y colpairs packed, UV naturally packed) ---
    #pragma unroll
    for (int it = 0; it < 3; it++) {
        int k = t + it * 256;                // 0..767
        u64t v[8];
        if (k < 256) {                       // Y: colpair items
            int q = (k >> 6) & 3, bx = k & 63;
            float* pl = sm + YOFF + q * 128 + bx * 2;
            #pragma unroll
            for (int r = 0; r < 8; r++) {
                float2 w = *(const float2*)(pl + r * 512);
                v[r] = pk2(w.x, w.y);
            }
            dct8p(v);
            const float4* qt = (const float4*)(sm + QL4);
            #pragma unroll
            for (int i2 = 0; i2 < 8; i2++) {
                float4 qq = qt[i2 * 4 + q];
                u64t q2 = pk2(qq.x, qq.y);
                u64t r2 = pk2(qq.z, qq.w);
                u64t x2 = v[i2];
                u64t yq = mul2(x2, r2);
                u64t rs = fma2(mul2(q2, dup2(-1.0f)), yq, x2);  // Newton
                yq = fma2(rs, r2, yq);
                float a, bb2; upk2(yq, a, bb2);
                v[i2] = mul2(pk2(rintf(a), rintf(bb2)), q2);
            }
            idct8p(v);
            #pragma unroll
            for (int r = 0; r < 8; r++) {
                float a, bb2; upk2(v[r], a, bb2);
                *(float2*)(pl + r * 512) = make_float2(a, bb2);
            }
        } else {                             // UV: one (u,v)-packed column
            int k2 = k - 256;                // 0..511
            int j = k2 >> 6, bx = k2 & 63;
            float* pl = sm + UVOFF + j * 128 + bx * 2;
            #pragma unroll
            for (int r = 0; r < 8; r++) {
                float2 w = *(const float2*)(pl + r * 1024);
                v[r] = pk2(w.x, w.y);
            }
            dct8p(v);
            const float2* qt = (const float2*)(sm + QC2);
            #pragma unroll
            for (int i2 = 0; i2 < 8; i2++) {
                float2 qq = qt[i2 * 8 + j];
                u64t q2 = dup2(qq.x);
                u64t r2 = dup2(qq.y);
                u64t x2 = v[i2];
                u64t yq = mul2(x2, r2);
                u64t rs = fma2(mul2(q2, dup2(-1.0f)), yq, x2);  // Newton
                yq = fma2(rs, r2, yq);
                float a, bb2; upk2(yq, a, bb2);
                v[i2] = mul2(pk2(rintf(a), rintf(bb2)), q2);
            }
            idct8p(v);
            #pragma unroll
            for (int r = 0; r < 8; r++) {
                float a, bb2; upk2(v[r], a, bb2);
                *(float2*)(pl + r * 1024) = make_float2(a, bb2);
            }
        }
    }
    __syncthreads();

    // ---- Phase C: ROW-IDCT + color inv -> store --------------------------
    float* orr = out + ((size_t)b * 3 + 0) * pstride + (size_t)by * 8 * NW;
    float* og  = orr + pstride;
    float* ob  = og + pstride;
    const u64t K128 = dup2(128.0f);
    #pragma unroll
    for (int it = 0; it < 2; it++) {
        int i  = t + it * 256;
        int r  = i >> 6, bx = i & 63;
        float Y[8]; u64t uv[8];
        const float* py = sm + YOFF + r * 512 + bx * 2;
        #pragma unroll
        for (int q = 0; q < 4; q++) {
            float2 w = *(const float2*)(py + q * 128);
            Y[2 * q] = w.x; Y[2 * q + 1] = w.y;
        }
        const float* pu = sm + UVOFF + r * 1024 + bx * 2;
        #pragma unroll
        for (int j = 0; j < 8; j++) {
            float2 w = *(const float2*)(pu + j * 128);
            uv[j] = pk2(w.x, w.y);
        }
        idct8(Y);
        idct8p(uv);
        const float inv255 = 1.0f / 255.0f;
        float* po = orr + r * NW + bx * 8;
        #pragma unroll
        for (int h = 0; h < 2; h++) {        // two half-rows of 4 px
            float4 R4, G4, B4;
            float* Rp = &R4.x; float* Gp = &G4.x; float* Bp = &B4.x;
            #pragma unroll
            for (int e = 0; e < 4; e++) {
                int j = h * 4 + e;
                float yy = __fadd_rn(Y[j], 128.0f);
                u64t w = sub2(add2(uv[j], K128), K128);
                float cbb, crr; upk2(w, cbb, crr);
                float rr = __fadd_rn(yy, __fmul_rn(1.402f, crr));
                float gg = __fsub_rn(__fsub_rn(yy, __fmul_rn(0.344136f, cbb)),
                                     __fmul_rn(0.714136f, crr));
                float bb = __fadd_rn(yy, __fmul_rn(1.772f, cbb));
                Rp[e] = __fmul_rn(rintf(fminf(fmaxf(rr, 0.0f), 255.0f)), inv255);
                Gp[e] = __fmul_rn(rintf(fminf(fmaxf(gg, 0.0f), 255.0f)), inv255);
                Bp[e] = __fmul_rn(rintf(fminf(fmaxf(bb, 0.0f), 255.0f)), inv255);
            }
            *(float4*)(po + h * 4)                 = R4;
            *(float4*)(po + h * 4 + (og - orr))    = G4;
            *(float4*)(po + h * 4 + (ob - orr))    = B4;
        }
    }
}

extern "C" void kernel_launch(void* const* d_in, const int* in_sizes, int n_in,
                              void* d_out, int out_size) {
    const float* in = (const float*)d_in[0];
    const int*   qp = (const int*)d_in[1];
    float*       out = (float*)d_out;
    (void)in_sizes; (void)n_in; (void)out_size;

    cudaFuncSetAttribute(jpeg_kernel,
                         cudaFuncAttributeMaxDynamicSharedMemorySize, SMEM_BYTES);
    dim3 grid(NH / 8, NB);          // 64 block-rows x 32 images = 2048 CTAs
    jpeg_kernel<<<grid, 256, SMEM_BYTES>>>(in, qp, out);
}